// round 4
// baseline (speedup 1.0000x reference)
#include <cuda_runtime.h>
#include <math.h>
#include <stdint.h>

// Problem constants
#define BATCH   256
#define NSLOTS  256
#define LIDX    765     // 3 * (NSLOTS - 1)

// Scratch (allocation-free: __device__ globals). Max activation = 256*512*256 floats.
__device__ float g_bufA[33554432];
__device__ float g_bufB[33554432];
__device__ float g_mean[BATCH];
__device__ float g_istd[BATCH];

// ---------------- helpers ----------------

__device__ __forceinline__ float mish_f(float x) {
    // softplus = max(x,0) + log1p(exp(-|x|))  (stable, matches jax.nn.softplus)
    float sp = fmaxf(x, 0.f) + log1pf(expf(-fabsf(x)));
    return x * tanhf(sp);
}

__device__ __forceinline__ void ffma2(unsigned long long& d,
                                      unsigned long long a,
                                      unsigned long long b) {
    asm("fma.rn.f32x2 %0, %1, %2, %0;" : "+l"(d) : "l"(a), "l"(b));
}
__device__ __forceinline__ unsigned long long pack2(float x, float y) {
    unsigned long long r;
    asm("mov.b64 %0, {%1, %2};" : "=l"(r) : "f"(x), "f"(y));
    return r;
}
__device__ __forceinline__ void unpack2(unsigned long long v, float& x, float& y) {
    asm("mov.b64 {%0, %1}, %2;" : "=f"(x), "=f"(y) : "l"(v));
}

// ---------------- kernel 1: linear + BN + mish ----------------
// out[b, m] = mish( BN( trees[b,:] . W_lin[m,:] + b_lin[m] ) ),  m in [0,4096)
// Tiled GEMM: M = feature (4096), N = batch (256). BM=64, BN=64, 16x16 threads, 4x4/thread.
__global__ __launch_bounds__(256)
void linear_kernel(const float* __restrict__ trees, const float* __restrict__ Wl,
                   const float* __restrict__ bl, const float* __restrict__ gamma,
                   const float* __restrict__ beta, const float* __restrict__ bmean,
                   const float* __restrict__ bvar, float* __restrict__ act0)
{
    const int m0 = blockIdx.x * 64;
    const int b0 = blockIdx.y * 64;
    __shared__ float As[16][65];
    __shared__ float Bs[16][65];
    const int tid = threadIdx.x, tx = tid & 15, ty = tid >> 4;
    float acc[4][4] = {};
    for (int k0 = 0; k0 < 512; k0 += 16) {
        #pragma unroll
        for (int i = tid; i < 64 * 16; i += 256) {
            int m = i >> 4, kk = i & 15;
            As[kk][m] = Wl[(size_t)(m0 + m) * 512 + k0 + kk];
        }
        #pragma unroll
        for (int i = tid; i < 64 * 16; i += 256) {
            int bb = i >> 4, kk = i & 15;
            Bs[kk][bb] = trees[(size_t)(b0 + bb) * 512 + k0 + kk];
        }
        __syncthreads();
        #pragma unroll
        for (int kk = 0; kk < 16; kk++) {
            float ra[4], rb[4];
            #pragma unroll
            for (int u = 0; u < 4; u++) ra[u] = As[kk][ty * 4 + u];
            #pragma unroll
            for (int v = 0; v < 4; v++) rb[v] = Bs[kk][tx * 4 + v];
            #pragma unroll
            for (int u = 0; u < 4; u++)
                #pragma unroll
                for (int v = 0; v < 4; v++)
                    acc[u][v] = fmaf(ra[u], rb[v], acc[u][v]);
        }
        __syncthreads();
    }
    #pragma unroll
    for (int u = 0; u < 4; u++) {
        int m = m0 + ty * 4 + u;
        float sc = rsqrtf(bvar[m] + 1e-5f) * gamma[m];
        float bm = bmean[m], bt = beta[m], bi = bl[m];
        #pragma unroll
        for (int v = 0; v < 4; v++) {
            int bb = b0 + tx * 4 + v;
            float y = acc[u][v] + bi;
            y = (y - bm) * sc + bt;
            act0[(size_t)bb * 4096 + m] = mish_f(y);
        }
    }
}

// ---------------- kernel 2: binary tree conv (gather-GEMM) ----------------
// raw[b, o, p] = (p==0) ? 0 : sum_{c,j} W[o,c,j] * act[b, c, idx[b, 3*(p-1)+j]] + bias[o]
// One CTA: batch b, BM output channels, all 256 positions.
// Per channel-chunk (8 channels): coalesced load into SMEM, LDS gather into Bs[24][256],
// then f32x2 FMA loop. Thread tile: TM rows x 16 cols (8 f32x2).
template<int CIN, int COUT, int BM, int TM>
__global__ __launch_bounds__(256, 2)
void conv_kernel(const float* __restrict__ act, const int* __restrict__ idx,
                 const float* __restrict__ W, const float* __restrict__ bias,
                 float* __restrict__ raw)
{
    constexpr int K  = 3 * CIN;
    constexpr int CB = 8;
    constexpr int KB = 3 * CB;   // 24
    __shared__ __align__(16) float Xs[CB][256];
    __shared__ __align__(16) float Bs[KB][256];
    __shared__ __align__(16) float As[KB][BM + 1];
    __shared__ int sidx[768];

    const int b  = blockIdx.x;
    const int m0 = blockIdx.y * BM;
    const int tid = threadIdx.x;
    const int tx = tid & 15, ty = tid >> 4;

    for (int i = tid; i < LIDX; i += 256) sidx[i] = idx[b * LIDX + i];

    unsigned long long acc[TM][8];
    #pragma unroll
    for (int tm = 0; tm < TM; tm++)
        #pragma unroll
        for (int q = 0; q < 8; q++) acc[tm][q] = 0ULL;

    const float* actb = act + (size_t)b * CIN * 256;
    const float* Wm   = W + (size_t)m0 * K;
    __syncthreads();  // sidx ready

    for (int c0 = 0; c0 < CIN; c0 += CB) {
        // Coalesced load of 8 channel rows
        #pragma unroll
        for (int i = tid; i < CB * 256; i += 256)
            Xs[i >> 8][i & 255] = actb[c0 * 256 + i];
        // Weight tile As[kk][m]
        #pragma unroll
        for (int i = tid; i < BM * KB; i += 256) {
            int m = i / KB, kk = i % KB;
            As[kk][m] = Wm[(size_t)m * K + c0 * 3 + kk];
        }
        __syncthreads();
        // Gather Bs from Xs via SMEM (col 0 is the zero-padding column)
        #pragma unroll
        for (int i = tid; i < KB * 256; i += 256) {
            int kk = i >> 8, p = i & 255;
            float v = 0.f;
            if (p) {
                int c = kk / 3, j = kk - 3 * (kk / 3);
                v = Xs[c][sidx[3 * (p - 1) + j]];
            }
            Bs[kk][p] = v;
        }
        __syncthreads();
        // f32x2 FMA main loop
        #pragma unroll
        for (int kk = 0; kk < KB; kk++) {
            const unsigned long long* brow =
                reinterpret_cast<const unsigned long long*>(&Bs[kk][0]);
            unsigned long long bf[8];
            #pragma unroll
            for (int q = 0; q < 8; q++) bf[q] = brow[tx + 16 * q];
            #pragma unroll
            for (int tm = 0; tm < TM; tm++) {
                float a = As[kk][ty * TM + tm];
                unsigned long long a2 = pack2(a, a);
                #pragma unroll
                for (int q = 0; q < 8; q++) ffma2(acc[tm][q], a2, bf[q]);
            }
        }
        __syncthreads();
    }

    // Epilogue: add bias, zero column 0
    #pragma unroll
    for (int tm = 0; tm < TM; tm++) {
        int m = ty * TM + tm;
        float bv = bias[m0 + m];
        float2* orow = reinterpret_cast<float2*>(
            raw + ((size_t)b * COUT + m0 + m) * 256);
        #pragma unroll
        for (int q = 0; q < 8; q++) {
            float lo, hi;
            unpack2(acc[tm][q], lo, hi);
            int f = tx + 16 * q;
            float2 v;
            v.x = (f == 0) ? 0.f : lo + bv;
            v.y = hi + bv;
            orow[f] = v;
        }
    }
}

// ---------------- kernel 3: per-batch mean / 1/(std+eps), ddof=1 ----------------
template<int COUT>
__global__ __launch_bounds__(256)
void reduce_kernel(const float* __restrict__ raw, float* __restrict__ mean,
                   float* __restrict__ istd)
{
    const int b = blockIdx.x;
    const float* p = raw + (size_t)b * COUT * 256;
    double s = 0.0, ss = 0.0;
    for (int i = threadIdx.x; i < COUT * 256; i += 256) {
        float v = p[i];
        s += (double)v;
        ss += (double)v * (double)v;
    }
    __shared__ double sh0[256];
    __shared__ double sh1[256];
    sh0[threadIdx.x] = s;
    sh1[threadIdx.x] = ss;
    __syncthreads();
    for (int off = 128; off > 0; off >>= 1) {
        if (threadIdx.x < off) {
            sh0[threadIdx.x] += sh0[threadIdx.x + off];
            sh1[threadIdx.x] += sh1[threadIdx.x + off];
        }
        __syncthreads();
    }
    if (threadIdx.x == 0) {
        const double cnt = (double)(COUT * 256);
        double m = sh0[0] / cnt;
        double var = (sh1[0] - cnt * m * m) / (cnt - 1.0);
        if (var < 0.0) var = 0.0;
        float sd = (float)sqrt(var);
        mean[b] = (float)m;
        istd[b] = 1.f / (sd + 1e-5f);
    }
}

// ---------------- kernel 4: normalize (+ optional mish) ----------------
template<int COUT, bool ACT>
__global__ __launch_bounds__(256)
void norm_kernel(const float* __restrict__ raw, const float* __restrict__ mean,
                 const float* __restrict__ istd, float* __restrict__ dst)
{
    constexpr int PER = COUT * 256;
    const int total = BATCH * PER;
    for (int i = blockIdx.x * blockDim.x + threadIdx.x; i < total;
         i += gridDim.x * blockDim.x) {
        int b = i / PER;
        float v = (raw[i] - mean[b]) * istd[b];
        if (ACT) v = mish_f(v);
        dst[i] = v;
    }
}

// ---------------- launch ----------------

extern "C" void kernel_launch(void* const* d_in, const int* in_sizes, int n_in,
                              void* d_out, int out_size)
{
    (void)in_sizes; (void)n_in; (void)out_size;
    const float* trees   = (const float*)d_in[0];
    const int*   indexes = (const int*)d_in[1];
    const float* W_lin   = (const float*)d_in[2];
    const float* b_lin   = (const float*)d_in[3];
    const float* bn_g    = (const float*)d_in[4];
    const float* bn_b    = (const float*)d_in[5];
    const float* bn_m    = (const float*)d_in[6];
    const float* bn_v    = (const float*)d_in[7];
    float* out = (float*)d_out;

    float *bufA, *bufB, *gmean, *gistd;
    cudaGetSymbolAddress((void**)&bufA,  g_bufA);
    cudaGetSymbolAddress((void**)&bufB,  g_bufB);
    cudaGetSymbolAddress((void**)&gmean, g_mean);
    cudaGetSymbolAddress((void**)&gistd, g_istd);

    // 1) linear + BN + mish -> bufA viewed as (B, 16, 256)
    linear_kernel<<<dim3(4096 / 64, BATCH / 64), 256>>>(
        trees, W_lin, b_lin, bn_g, bn_b, bn_m, bn_v, bufA);

    // 2) six tree-conv layers; conv: bufA -> bufB (raw); norm: bufB -> bufA (or d_out)
#define LAYER(I, CIN, COUT, BM, TM, ACT, DST)                                     \
    conv_kernel<CIN, COUT, BM, TM><<<dim3(BATCH, COUT / BM), 256>>>(              \
        bufA, indexes, (const float*)d_in[8 + 2 * I],                             \
        (const float*)d_in[9 + 2 * I], bufB);                                     \
    reduce_kernel<COUT><<<BATCH, 256>>>(bufB, gmean, gistd);                      \
    norm_kernel<COUT, ACT><<<2048, 256>>>(bufB, gmean, gistd, DST);

    LAYER(0,  16,  32, 32, 2, false, bufA)
    LAYER(1,  32,  64, 64, 4, true,  bufA)
    LAYER(2,  64, 128, 64, 4, true,  bufA)
    LAYER(3, 128, 256, 64, 4, true,  bufA)
    LAYER(4, 256, 512, 64, 4, true,  bufA)
    LAYER(5, 512, 512, 64, 4, true,  out)
#undef LAYER
}

// round 5
// speedup vs baseline: 1.1911x; 1.1911x over previous
#include <cuda_runtime.h>
#include <math.h>
#include <stdint.h>

#define BATCH   256
#define LIDX    765

// Scratch (allocation-free __device__ globals)
__device__ float  g_bufA[33554432];
__device__ float  g_bufB[33554432];
__device__ double g_stats[2 * BATCH];
__device__ float  g_mean[BATCH];
__device__ float  g_istd[BATCH];

// ---------------- helpers ----------------

// mish(x) = x*tanh(softplus(x)) = x*(e^2+2e)/(e^2+2e+2), e = exp(x)
__device__ __forceinline__ float mish_f(float x) {
    if (x > 15.f) return x;
    float e = __expf(x);
    float t = e * (e + 2.f);
    return __fdividef(x * t, t + 2.f);
}

__device__ __forceinline__ void ffma2(unsigned long long& d,
                                      unsigned long long a,
                                      unsigned long long b) {
    asm("fma.rn.f32x2 %0, %1, %2, %0;" : "+l"(d) : "l"(a), "l"(b));
}
__device__ __forceinline__ unsigned long long pack2(float x, float y) {
    unsigned long long r;
    asm("mov.b64 %0, {%1, %2};" : "=l"(r) : "f"(x), "f"(y));
    return r;
}
__device__ __forceinline__ void unpack2(unsigned long long v, float& x, float& y) {
    asm("mov.b64 {%0, %1}, %2;" : "=f"(x), "=f"(y) : "l"(v));
}

// ---------------- kernel 1: linear + BN + mish ----------------
__global__ __launch_bounds__(256)
void linear_kernel(const float* __restrict__ trees, const float* __restrict__ Wl,
                   const float* __restrict__ bl, const float* __restrict__ gamma,
                   const float* __restrict__ beta, const float* __restrict__ bmean,
                   const float* __restrict__ bvar, float* __restrict__ act0)
{
    const int m0 = blockIdx.x * 64;
    const int b0 = blockIdx.y * 64;
    __shared__ float As[16][65];
    __shared__ float Bs[16][65];
    const int tid = threadIdx.x, tx = tid & 15, ty = tid >> 4;
    float acc[4][4] = {};
    for (int k0 = 0; k0 < 512; k0 += 16) {
        #pragma unroll
        for (int i = tid; i < 64 * 16; i += 256) {
            int m = i >> 4, kk = i & 15;
            As[kk][m] = Wl[(size_t)(m0 + m) * 512 + k0 + kk];
        }
        #pragma unroll
        for (int i = tid; i < 64 * 16; i += 256) {
            int bb = i >> 4, kk = i & 15;
            Bs[kk][bb] = trees[(size_t)(b0 + bb) * 512 + k0 + kk];
        }
        __syncthreads();
        #pragma unroll
        for (int kk = 0; kk < 16; kk++) {
            float ra[4], rb[4];
            #pragma unroll
            for (int u = 0; u < 4; u++) ra[u] = As[kk][ty * 4 + u];
            #pragma unroll
            for (int v = 0; v < 4; v++) rb[v] = Bs[kk][tx * 4 + v];
            #pragma unroll
            for (int u = 0; u < 4; u++)
                #pragma unroll
                for (int v = 0; v < 4; v++)
                    acc[u][v] = fmaf(ra[u], rb[v], acc[u][v]);
        }
        __syncthreads();
    }
    #pragma unroll
    for (int u = 0; u < 4; u++) {
        int m = m0 + ty * 4 + u;
        float sc = rsqrtf(bvar[m] + 1e-5f) * gamma[m];
        float bm = bmean[m], bt = beta[m], bi = bl[m];
        #pragma unroll
        for (int v = 0; v < 4; v++) {
            int bb = b0 + tx * 4 + v;
            float y = acc[u][v] + bi;
            y = (y - bm) * sc + bt;
            act0[(size_t)bb * 4096 + m] = mish_f(y);
        }
    }
}

// ---------------- fused conv: input transform + gather-GEMM + stats ----------------
// XFORM: 0 = identity, 1 = (x-mean)*istd, 2 = mish((x-mean)*istd)
// Software pipeline: double-buffered Bs/As; gather(n+1) overlaps FMA(n).
template<int CIN, int COUT, int BM, int TM, int XFORM>
__global__ __launch_bounds__(256, 1)
void conv_kernel(const float* __restrict__ act, const int* __restrict__ idx,
                 const float* __restrict__ W, const float* __restrict__ bias,
                 const float* __restrict__ mean, const float* __restrict__ istd,
                 float* __restrict__ raw, double* __restrict__ stats)
{
    static_assert(BM == 16 * TM, "tile mismatch");
    constexpr int CB = 8;
    constexpr int KB = 24;
    constexpr int NC = CIN / CB;
    constexpr int K3 = 3 * CIN;

    extern __shared__ float smem[];
    float* Bsm  = smem;                    // [2][KB][256]
    float* Xs   = Bsm + 2 * KB * 256;      // [CB][256]  (aliased as double[512] in epilogue)
    float* Asm  = Xs + CB * 256;           // [2][BM][KB]
    int*   sidx = (int*)(Asm + 2 * BM * KB); // [768]

    const int b   = blockIdx.x;
    const int m0  = blockIdx.y * BM;
    const int tid = threadIdx.x;
    const int tx  = tid & 15, ty = tid >> 4;

    const float* actb = act + (size_t)b * CIN * 256;
    const float* Wrow = W + (size_t)m0 * K3;

    float mb = 0.f, isb = 1.f;
    if (XFORM) { mb = mean[b]; isb = istd[b]; }

    for (int i = tid; i < LIDX; i += 256) sidx[i] = idx[b * LIDX + i];

    unsigned long long acc[TM][8];
    #pragma unroll
    for (int u = 0; u < TM; u++)
        #pragma unroll
        for (int q = 0; q < 8; q++) acc[u][q] = 0ULL;

    // ---- fill: load X chunk (with transform) + W chunk into buf ----
    auto fill = [&](int chunk, int buf) {
        const float4* src = reinterpret_cast<const float4*>(actb + (size_t)chunk * CB * 256);
        #pragma unroll
        for (int r = 0; r < 2; r++) {
            float4 v = src[tid + 256 * r];
            if (XFORM) {
                v.x = (v.x - mb) * isb; v.y = (v.y - mb) * isb;
                v.z = (v.z - mb) * isb; v.w = (v.w - mb) * isb;
                if (XFORM == 2) {
                    v.x = mish_f(v.x); v.y = mish_f(v.y);
                    v.z = mish_f(v.z); v.w = mish_f(v.w);
                }
            }
            reinterpret_cast<float4*>(Xs)[tid + 256 * r] = v;
        }
        float* Ab = Asm + buf * BM * KB;
        #pragma unroll
        for (int i = tid; i < BM * 6; i += 256) {
            int m = i / 6, k4 = i % 6;
            float4 w = *reinterpret_cast<const float4*>(
                Wrow + (size_t)m * K3 + chunk * KB + k4 * 4);
            *reinterpret_cast<float4*>(&Ab[m * KB + k4 * 4]) = w;
        }
    };

    // per-thread gather sources (p == tid); loaded after first sync
    int s0 = 0, s1 = 0, s2 = 0;

    auto gather = [&](int buf) {
        float* Bb = Bsm + buf * KB * 256;
        if (tid) {
            #pragma unroll
            for (int t = 0; t < KB; t++) {
                int c = t / 3, j = t - 3 * (t / 3);
                int s = (j == 0) ? s0 : (j == 1) ? s1 : s2;
                Bb[t * 256 + tid] = Xs[c * 256 + s];
            }
        } else {
            #pragma unroll
            for (int t = 0; t < KB; t++) Bb[t * 256] = 0.f;
        }
    };

    auto fmastep = [&](int buf) {
        const unsigned long long* Bb =
            reinterpret_cast<const unsigned long long*>(Bsm + buf * KB * 256);
        const float* Ab = Asm + buf * BM * KB + (ty * TM) * KB;
        #pragma unroll
        for (int kk = 0; kk < KB; kk++) {
            unsigned long long bf[8];
            #pragma unroll
            for (int q = 0; q < 8; q++) bf[q] = Bb[kk * 128 + tx + 16 * q];
            #pragma unroll
            for (int u = 0; u < TM; u++) {
                float a = Ab[u * KB + kk];
                unsigned long long a2 = pack2(a, a);
                #pragma unroll
                for (int q = 0; q < 8; q++) ffma2(acc[u][q], a2, bf[q]);
            }
        }
    };

    // ---- pipelined main loop ----
    fill(0, 0);
    __syncthreads();
    if (tid) {
        s0 = sidx[3 * tid - 3];
        s1 = sidx[3 * tid - 2];
        s2 = sidx[3 * tid - 1];
    }
    gather(0);
    int cur = 0;
    for (int c = 1; c <= NC; c++) {
        __syncthreads();                    // gather(c-1) complete; Xs free
        if (c < NC) fill(c, cur ^ 1);
        __syncthreads();                    // Xs(c) ready
        if (c < NC) gather(cur ^ 1);        // overlaps with fmastep below (warp-level)
        fmastep(cur);
        cur ^= 1;
    }

    // ---- epilogue: bias, zero col 0, write raw, fused LN stats ----
    float bsum = 0.f, bssq = 0.f;
    #pragma unroll
    for (int u = 0; u < TM; u++) {
        int m = m0 + ty * TM + u;
        float bv = bias[m];
        float2* orow = reinterpret_cast<float2*>(raw + ((size_t)b * COUT + m) * 256);
        #pragma unroll
        for (int q = 0; q < 8; q++) {
            float lo, hi;
            unpack2(acc[u][q], lo, hi);
            int f = tx + 16 * q;
            float2 v;
            v.x = (f == 0) ? 0.f : lo + bv;
            v.y = hi + bv;
            orow[f] = v;
            bsum += v.x + v.y;
            bssq += v.x * v.x + v.y * v.y;
        }
    }
    __syncthreads();
    double* sh = reinterpret_cast<double*>(Xs);   // 512 doubles fit in Xs (8KB)
    sh[tid] = (double)bsum;
    sh[256 + tid] = (double)bssq;
    __syncthreads();
    #pragma unroll
    for (int off = 128; off > 0; off >>= 1) {
        if (tid < off) {
            sh[tid] += sh[tid + off];
            sh[256 + tid] += sh[256 + tid + off];
        }
        __syncthreads();
    }
    if (tid == 0) {
        atomicAdd(&stats[b], sh[0]);
        atomicAdd(&stats[BATCH + b], sh[256]);
    }
}

// ---------------- finalize per-batch LN statistics ----------------
__global__ void finalize_kernel(const double* __restrict__ stats,
                                float* __restrict__ mean, float* __restrict__ istd,
                                double cnt)
{
    int b = threadIdx.x;
    double s = stats[b], ss = stats[BATCH + b];
    double m = s / cnt;
    double var = (ss - cnt * m * m) / (cnt - 1.0);
    if (var < 0.0) var = 0.0;
    mean[b] = (float)m;
    istd[b] = 1.f / ((float)sqrt(var) + 1e-5f);
}

// ---------------- final normalize + mish -> out ----------------
__global__ __launch_bounds__(256)
void norm_final(const float* __restrict__ raw, const float* __restrict__ mean,
                const float* __restrict__ istd, float* __restrict__ out)
{
    const int PER4 = 512 * 256 / 4;
    const int total4 = BATCH * PER4;
    const float4* src = reinterpret_cast<const float4*>(raw);
    float4* dst = reinterpret_cast<float4*>(out);
    for (int i = blockIdx.x * blockDim.x + threadIdx.x; i < total4;
         i += gridDim.x * blockDim.x) {
        int b = i / PER4;
        float mb = mean[b], isb = istd[b];
        float4 v = src[i];
        v.x = mish_f((v.x - mb) * isb);
        v.y = mish_f((v.y - mb) * isb);
        v.z = mish_f((v.z - mb) * isb);
        v.w = mish_f((v.w - mb) * isb);
        dst[i] = v;
    }
}

// ---------------- launch ----------------

static constexpr int conv_smem(int BM) {
    return (2 * 24 * 256 + 8 * 256 + 2 * BM * 24) * 4 + 768 * 4;
}

extern "C" void kernel_launch(void* const* d_in, const int* in_sizes, int n_in,
                              void* d_out, int out_size)
{
    (void)in_sizes; (void)n_in; (void)out_size;
    const float* trees   = (const float*)d_in[0];
    const int*   indexes = (const int*)d_in[1];
    const float* W_lin   = (const float*)d_in[2];
    const float* b_lin   = (const float*)d_in[3];
    const float* bn_g    = (const float*)d_in[4];
    const float* bn_b    = (const float*)d_in[5];
    const float* bn_m    = (const float*)d_in[6];
    const float* bn_v    = (const float*)d_in[7];
    float* out = (float*)d_out;

    float *bufA, *bufB, *gmean, *gistd;
    double* stats;
    cudaGetSymbolAddress((void**)&bufA,  g_bufA);
    cudaGetSymbolAddress((void**)&bufB,  g_bufB);
    cudaGetSymbolAddress((void**)&gmean, g_mean);
    cudaGetSymbolAddress((void**)&gistd, g_istd);
    cudaGetSymbolAddress((void**)&stats, g_stats);

    cudaFuncSetAttribute(conv_kernel<16, 32, 32, 2, 0>,
        cudaFuncAttributeMaxDynamicSharedMemorySize, conv_smem(32));
    cudaFuncSetAttribute(conv_kernel<32, 64, 64, 4, 1>,
        cudaFuncAttributeMaxDynamicSharedMemorySize, conv_smem(64));
    cudaFuncSetAttribute(conv_kernel<64, 128, 128, 8, 2>,
        cudaFuncAttributeMaxDynamicSharedMemorySize, conv_smem(128));
    cudaFuncSetAttribute(conv_kernel<128, 256, 128, 8, 2>,
        cudaFuncAttributeMaxDynamicSharedMemorySize, conv_smem(128));
    cudaFuncSetAttribute(conv_kernel<256, 512, 128, 8, 2>,
        cudaFuncAttributeMaxDynamicSharedMemorySize, conv_smem(128));
    cudaFuncSetAttribute(conv_kernel<512, 512, 128, 8, 2>,
        cudaFuncAttributeMaxDynamicSharedMemorySize, conv_smem(128));

    // 1) linear + BN + mish -> bufA (viewed as (B, 16, 256))
    linear_kernel<<<dim3(64, 4), 256>>>(
        trees, W_lin, b_lin, bn_g, bn_b, bn_m, bn_v, bufA);

#define CONVL(I, CIN, COUT, BM, TM, XF, SRC, DST)                                   \
    cudaMemsetAsync(stats, 0, sizeof(double) * 2 * BATCH);                          \
    conv_kernel<CIN, COUT, BM, TM, XF>                                              \
        <<<dim3(BATCH, COUT / BM), 256, conv_smem(BM)>>>(                           \
            SRC, indexes, (const float*)d_in[8 + 2 * I],                            \
            (const float*)d_in[9 + 2 * I], gmean, gistd, DST, stats);               \
    finalize_kernel<<<1, BATCH>>>(stats, gmean, gistd, (double)(COUT * 256));

    CONVL(0,  16,  32,  32, 2, 0, bufA, bufB)
    CONVL(1,  32,  64,  64, 4, 1, bufB, bufA)
    CONVL(2,  64, 128, 128, 8, 2, bufA, bufB)
    CONVL(3, 128, 256, 128, 8, 2, bufB, bufA)
    CONVL(4, 256, 512, 128, 8, 2, bufA, bufB)
    CONVL(5, 512, 512, 128, 8, 2, bufB, bufA)
#undef CONVL

    // final: out = mish(LN(raw5))
    norm_final<<<2048, 256>>>(bufA, gmean, gistd, out);
}